// round 4
// baseline (speedup 1.0000x reference)
#include <cuda_runtime.h>
#include <math.h>

// Problem constants
#define NB    256   // batch
#define CIN   256   // input channels
#define HW    784   // 28*28 spatial
#define DD    64    // prototype channel dim
#define PP    200   // num prototypes
#define NCLS  10

constexpr int STILE   = 128;  // spatial positions per sub-tile
constexpr int KC      = 32;   // k-chunk for GEMM1
constexpr int THREADS = 512;

// Shared memory layout (float offsets)
constexpr int OFF_W1  = 0;                       // [64][256]
constexpr int OFF_W2  = OFF_W1 + DD * CIN;       // [64][64]
constexpr int OFF_P   = OFF_W2 + DD * DD;        // [200][64]
constexpr int OFF_P2  = OFF_P  + PP * DD;        // [200]
constexpr int OFF_B1  = OFF_P2 + PP;             // [64]
constexpr int OFF_B2  = OFF_B1 + DD;             // [64]
constexpr int OFF_XS  = OFF_B2 + DD;             // [KC][STILE]
constexpr int OFF_HS  = OFF_XS + KC * STILE;     // [64][STILE]
constexpr int OFF_FS  = OFF_HS + DD * STILE;     // [64][STILE]
constexpr int OFF_X2  = OFF_FS + DD * STILE;     // [STILE]
constexpr int OFF_MIN = OFF_X2 + STILE;          // [200] (int bits)
constexpr int SMEM_FLOATS = OFF_MIN + PP;
constexpr int SMEM_BYTES  = SMEM_FLOATS * 4;     // ~217.7 KB

typedef unsigned long long u64;

// ---- packed f32x2 helpers (FFMA2 — PTX-only on sm_103a) ----
__device__ __forceinline__ u64 pack2(float lo, float hi) {
    u64 r; asm("mov.b64 %0, {%1,%2};" : "=l"(r) : "f"(lo), "f"(hi)); return r;
}
__device__ __forceinline__ u64 dup2(float v) {
    u64 r; asm("mov.b64 %0, {%1,%1};" : "=l"(r) : "f"(v)); return r;
}
__device__ __forceinline__ void fma2(u64& d, u64 a, u64 b) {
    asm("fma.rn.f32x2 %0, %1, %2, %0;" : "+l"(d) : "l"(a), "l"(b));
}
__device__ __forceinline__ float2 unpk(u64 v) {
    float lo, hi; asm("mov.b64 {%0,%1}, %2;" : "=f"(lo), "=f"(hi) : "l"(v));
    return make_float2(lo, hi);
}

__global__ __launch_bounds__(THREADS, 1)
void proto_fused_kernel(const float* __restrict__ x,
                        const float* __restrict__ W1,
                        const float* __restrict__ b1,
                        const float* __restrict__ W2,
                        const float* __restrict__ b2,
                        const float* __restrict__ proto,
                        const float* __restrict__ lastW,
                        const float* __restrict__ lastB,
                        float* __restrict__ out_logits,
                        float* __restrict__ out_mind)
{
    extern __shared__ float sm[];
    float* sW1 = sm + OFF_W1;
    float* sW2 = sm + OFF_W2;
    float* sP  = sm + OFF_P;
    float* sP2 = sm + OFF_P2;
    float* sB1 = sm + OFF_B1;
    float* sB2 = sm + OFF_B2;
    float* sXS = sm + OFF_XS;
    float* sHS = sm + OFF_HS;
    float* sFS = sm + OFF_FS;
    float* sX2 = sm + OFF_X2;
    int*   sMind = (int*)(sm + OFF_MIN);

    const int tid   = threadIdx.x;
    const int n     = blockIdx.x;
    const int lane  = tid & 31;
    const int grp   = tid >> 5;      // 0..15
    const int dbase = grp * 4;       // 4 output-channel columns per thread
    const int sbase = lane * 4;      // 4 spatial positions per thread

    // ---- Cooperative load of persistent weights into smem ----
    {
        const float4* g = (const float4*)W1;
        float4* s4 = (float4*)sW1;
        for (int i = tid; i < (DD * CIN) / 4; i += THREADS) s4[i] = g[i];
    }
    {
        const float4* g = (const float4*)W2;
        float4* s4 = (float4*)sW2;
        for (int i = tid; i < (DD * DD) / 4; i += THREADS) s4[i] = g[i];
    }
    {
        const float4* g = (const float4*)proto;
        float4* s4 = (float4*)sP;
        for (int i = tid; i < (PP * DD) / 4; i += THREADS) s4[i] = g[i];
    }
    if (tid < DD) { sB1[tid] = b1[tid]; sB2[tid] = b2[tid]; }
    if (tid < PP) sMind[tid] = 0x7F7FFFFF;   // FLT_MAX bits (all dists >= 0)
    __syncthreads();
    if (tid < PP) {   // ||p||^2 per prototype
        const float* pr = sP + tid * DD;
        float s = 0.f;
        #pragma unroll 8
        for (int d = 0; d < DD; d++) s += pr[d] * pr[d];
        sP2[tid] = s;
    }
    __syncthreads();

    const float* xg = x + (size_t)n * CIN * HW;

    // ---- 7 spatial sub-tiles of 128 positions ----
    for (int st = 0; st < 7; st++) {
        const int s0 = st * STILE;
        const int validCnt = HW - s0;   // >=128 except last tile (16)

        // ===== GEMM1: h[s][d] = relu(sum_c x[c][s] * W1[d][c] + b1[d]) =====
        u64 acc01[4], acc23[4];
        #pragma unroll
        for (int i = 0; i < 4; i++) { acc01[i] = 0ull; acc23[i] = 0ull; }

        for (int kc = 0; kc < CIN / KC; kc++) {
            __syncthreads();   // protect sXS vs prior chunk's readers
            // stage x chunk [KC][STILE], coalesced rows of 128
            #pragma unroll
            for (int j = 0; j < (KC * STILE) / THREADS; j++) {
                int i  = j * THREADS + tid;
                int k  = i >> 7;         // /128
                int sl = i & 127;
                int gs = s0 + sl;
                sXS[i] = (gs < HW) ? xg[(kc * KC + k) * HW + gs] : 0.f;
            }
            __syncthreads();
            const float* wrow = sW1 + dbase * CIN + kc * KC;
            #pragma unroll
            for (int k4 = 0; k4 < KC; k4 += 4) {
                float4 w4[4];
                #pragma unroll
                for (int di = 0; di < 4; di++)
                    w4[di] = *(const float4*)(wrow + di * CIN + k4);
                #pragma unroll
                for (int kk = 0; kk < 4; kk++) {
                    const float4 a = *(const float4*)(sXS + (k4 + kk) * STILE + sbase);
                    const u64 aA = pack2(a.x, a.y);
                    const u64 aB = pack2(a.z, a.w);
                    #pragma unroll
                    for (int di = 0; di < 4; di++) {
                        const u64 wd = dup2(((const float*)&w4[di])[kk]);
                        fma2(acc01[di], aA, wd);
                        fma2(acc23[di], aB, wd);
                    }
                }
            }
        }
        // relu(+b1), store h transposed [d][s]; zero per-position ||f||^2
        #pragma unroll
        for (int di = 0; di < 4; di++) {
            const float b = sB1[dbase + di];
            const float2 p01 = unpk(acc01[di]);
            const float2 p23 = unpk(acc23[di]);
            float4 v;
            v.x = fmaxf(p01.x + b, 0.f);
            v.y = fmaxf(p01.y + b, 0.f);
            v.z = fmaxf(p23.x + b, 0.f);
            v.w = fmaxf(p23.y + b, 0.f);
            *(float4*)(sHS + (dbase + di) * STILE + sbase) = v;
        }
        if (tid < STILE) sX2[tid] = 0.f;
        __syncthreads();

        // ===== GEMM2: f[s][d2] = sigmoid(sum_d1 h[d1][s] * W2[d2][d1] + b2) =====
        u64 bacc01[4], bacc23[4];
        #pragma unroll
        for (int i = 0; i < 4; i++) { bacc01[i] = 0ull; bacc23[i] = 0ull; }
        {
            const float* wrow = sW2 + dbase * DD;
            #pragma unroll
            for (int k4 = 0; k4 < DD; k4 += 4) {
                float4 w4[4];
                #pragma unroll
                for (int di = 0; di < 4; di++)
                    w4[di] = *(const float4*)(wrow + di * DD + k4);
                #pragma unroll
                for (int kk = 0; kk < 4; kk++) {
                    const float4 a = *(const float4*)(sHS + (k4 + kk) * STILE + sbase);
                    const u64 aA = pack2(a.x, a.y);
                    const u64 aB = pack2(a.z, a.w);
                    #pragma unroll
                    for (int di = 0; di < 4; di++) {
                        const u64 wd = dup2(((const float*)&w4[di])[kk]);
                        fma2(bacc01[di], aA, wd);
                        fma2(bacc23[di], aB, wd);
                    }
                }
            }
        }
        // sigmoid, accumulate ||f||^2 per position, store f transposed [d][s]
        float xpart[4] = {0.f, 0.f, 0.f, 0.f};
        #pragma unroll
        for (int di = 0; di < 4; di++) {
            const float b = sB2[dbase + di];
            const float2 p01 = unpk(bacc01[di]);
            const float2 p23 = unpk(bacc23[di]);
            float4 v;
            v.x = 1.f / (1.f + __expf(-(p01.x + b)));
            v.y = 1.f / (1.f + __expf(-(p01.y + b)));
            v.z = 1.f / (1.f + __expf(-(p23.x + b)));
            v.w = 1.f / (1.f + __expf(-(p23.y + b)));
            xpart[0] += v.x * v.x;
            xpart[1] += v.y * v.y;
            xpart[2] += v.z * v.z;
            xpart[3] += v.w * v.w;
            *(float4*)(sFS + (dbase + di) * STILE + sbase) = v;
        }
        #pragma unroll
        for (int si = 0; si < 4; si++) atomicAdd(&sX2[sbase + si], xpart[si]);
        __syncthreads();

        // ===== GEMM3: xp[s][p]; dist = relu(x2 - 2*xp + p2); running min =====
        // 8 prototypes per thread, 2 chunks (128 + 72); chunk 1 skipped by grp>8.
        float xv[4];
        #pragma unroll
        for (int si = 0; si < 4; si++) xv[si] = sX2[sbase + si];

        #pragma unroll
        for (int pc = 0; pc < 2; pc++) {
            const int pbase = pc * 128 + grp * 8;   // warp-uniform
            if (pbase >= PP) break;
            u64 pacc01[8], pacc23[8];
            #pragma unroll
            for (int i = 0; i < 8; i++) { pacc01[i] = 0ull; pacc23[i] = 0ull; }
            const float* prow = sP + pbase * DD;
            #pragma unroll
            for (int k4 = 0; k4 < DD; k4 += 4) {
                u64 aA[4], aB[4];
                #pragma unroll
                for (int kk = 0; kk < 4; kk++) {
                    const float4 a = *(const float4*)(sFS + (k4 + kk) * STILE + sbase);
                    aA[kk] = pack2(a.x, a.y);
                    aB[kk] = pack2(a.z, a.w);
                }
                #pragma unroll
                for (int pj = 0; pj < 8; pj++) {
                    const float4 w4 = *(const float4*)(prow + pj * DD + k4);
                    #pragma unroll
                    for (int kk = 0; kk < 4; kk++) {
                        const u64 wd = dup2(((const float*)&w4)[kk]);
                        fma2(pacc01[pj], aA[kk], wd);
                        fma2(pacc23[pj], aB[kk], wd);
                    }
                }
            }
            #pragma unroll
            for (int pj = 0; pj < 8; pj++) {
                const float pn2 = sP2[pbase + pj];
                const float2 d01 = unpk(pacc01[pj]);
                const float2 d23 = unpk(pacc23[pj]);
                const float dv[4] = {d01.x, d01.y, d23.x, d23.y};
                float m = 3.402823466e+38f;
                #pragma unroll
                for (int si = 0; si < 4; si++) {
                    float d = xv[si] - 2.f * dv[si] + pn2;
                    d = fmaxf(d, 0.f);
                    if (sbase + si < validCnt) m = fminf(m, d);
                }
                #pragma unroll
                for (int o = 16; o > 0; o >>= 1)
                    m = fminf(m, __shfl_xor_sync(0xffffffffu, m, o));
                if (lane == 0)
                    atomicMin(&sMind[pbase + pj], __float_as_int(m));
            }
        }
        // no sync needed here: next iteration syncs before touching shared state
    }
    __syncthreads();

    // ---- Outputs ----
    if (tid < PP)
        out_mind[n * PP + tid] = __int_as_float(sMind[tid]);
    if (tid < NCLS * 32) {
        const int cls = tid >> 5;
        float ssum = 0.f;
        for (int p = lane; p < PP; p += 32)
            ssum += __int_as_float(sMind[p]) * lastW[cls * PP + p];
        #pragma unroll
        for (int o = 16; o > 0; o >>= 1)
            ssum += __shfl_xor_sync(0xffffffffu, ssum, o);
        if (lane == 0)
            out_logits[n * NCLS + cls] = lastB[cls] - ssum;   // act = -min_dist
    }
}

extern "C" void kernel_launch(void* const* d_in, const int* in_sizes, int n_in,
                              void* d_out, int out_size) {
    (void)in_sizes; (void)n_in; (void)out_size;
    const float* x      = (const float*)d_in[0];
    const float* W1     = (const float*)d_in[1];
    const float* b1     = (const float*)d_in[2];
    const float* W2     = (const float*)d_in[3];
    const float* b2     = (const float*)d_in[4];
    const float* proto  = (const float*)d_in[5];
    const float* lastW  = (const float*)d_in[6];
    const float* lastB  = (const float*)d_in[7];
    float* out        = (float*)d_out;
    float* out_logits = out;                 // (256,10)
    float* out_mind   = out + NB * NCLS;     // (256,200)

    cudaFuncSetAttribute(proto_fused_kernel,
                         cudaFuncAttributeMaxDynamicSharedMemorySize, SMEM_BYTES);
    proto_fused_kernel<<<NB, THREADS, SMEM_BYTES>>>(
        x, W1, b1, W2, b2, proto, lastW, lastB, out_logits, out_mind);
}

// round 5
// speedup vs baseline: 1.3161x; 1.3161x over previous
#include <cuda_runtime.h>
#include <math.h>

// Problem constants
#define NB    256   // batch
#define CIN   256   // input channels
#define HW    784   // 28*28 spatial
#define DD    64    // prototype channel dim
#define PP    200   // num prototypes
#define NCLS  10

constexpr int STILE   = 128;  // spatial positions per sub-tile
constexpr int KC      = 32;   // k-chunk for GEMM1
constexpr int THREADS = 512;

// Shared memory layout (float offsets)
constexpr int OFF_W1  = 0;                       // [64][256]
constexpr int OFF_W2  = OFF_W1 + DD * CIN;       // [64][64]
constexpr int OFF_P   = OFF_W2 + DD * DD;        // [200][64]
constexpr int OFF_P2  = OFF_P  + PP * DD;        // [200]
constexpr int OFF_B1  = OFF_P2 + PP;             // [64]
constexpr int OFF_B2  = OFF_B1 + DD;             // [64]
constexpr int OFF_XS  = OFF_B2 + DD;             // [KC][STILE]
constexpr int OFF_HS  = OFF_XS + KC * STILE;     // [64][STILE]
constexpr int OFF_FS  = OFF_HS + DD * STILE;     // [64][STILE]
constexpr int OFF_X2  = OFF_FS + DD * STILE;     // [STILE]
constexpr int OFF_MIN = OFF_X2 + STILE;          // [200] (int bits)
constexpr int SMEM_FLOATS = OFF_MIN + PP;
constexpr int SMEM_BYTES  = SMEM_FLOATS * 4;     // ~217.7 KB

typedef unsigned long long u64;

// ---- packed f32x2 helpers (FFMA2 — PTX-only on sm_103a) ----
__device__ __forceinline__ u64 pack2(float lo, float hi) {
    u64 r; asm("mov.b64 %0, {%1,%2};" : "=l"(r) : "f"(lo), "f"(hi)); return r;
}
__device__ __forceinline__ u64 dup2(float v) {
    u64 r; asm("mov.b64 %0, {%1,%1};" : "=l"(r) : "f"(v)); return r;
}
__device__ __forceinline__ void fma2(u64& d, u64 a, u64 b) {
    asm("fma.rn.f32x2 %0, %1, %2, %0;" : "+l"(d) : "l"(a), "l"(b));
}
__device__ __forceinline__ float2 unpk(u64 v) {
    float lo, hi; asm("mov.b64 {%0,%1}, %2;" : "=f"(lo), "=f"(hi) : "l"(v));
    return make_float2(lo, hi);
}

__global__ __launch_bounds__(THREADS, 1)
void proto_fused_kernel(const float* __restrict__ x,
                        const float* __restrict__ W1,
                        const float* __restrict__ b1,
                        const float* __restrict__ W2,
                        const float* __restrict__ b2,
                        const float* __restrict__ proto,
                        const float* __restrict__ lastW,
                        const float* __restrict__ lastB,
                        float* __restrict__ out_logits,
                        float* __restrict__ out_mind)
{
    extern __shared__ float sm[];
    float* sW1 = sm + OFF_W1;
    float* sW2 = sm + OFF_W2;
    float* sP  = sm + OFF_P;
    float* sP2 = sm + OFF_P2;
    float* sB1 = sm + OFF_B1;
    float* sB2 = sm + OFF_B2;
    float* sXS = sm + OFF_XS;
    float* sHS = sm + OFF_HS;
    float* sFS = sm + OFF_FS;
    float* sX2 = sm + OFF_X2;
    int*   sMind = (int*)(sm + OFF_MIN);

    const int tid   = threadIdx.x;
    const int n     = blockIdx.x;
    const int lane  = tid & 31;
    const int grp   = tid >> 5;      // 0..15
    const int dbase = grp * 4;       // 4 output-channel columns per thread
    const int sbase = lane * 4;      // 4 spatial positions per thread

    // ---- Cooperative load of persistent weights into smem ----
    {
        const float4* g = (const float4*)W1;
        float4* s4 = (float4*)sW1;
        for (int i = tid; i < (DD * CIN) / 4; i += THREADS) s4[i] = g[i];
    }
    {
        const float4* g = (const float4*)W2;
        float4* s4 = (float4*)sW2;
        for (int i = tid; i < (DD * DD) / 4; i += THREADS) s4[i] = g[i];
    }
    {
        const float4* g = (const float4*)proto;
        float4* s4 = (float4*)sP;
        for (int i = tid; i < (PP * DD) / 4; i += THREADS) s4[i] = g[i];
    }
    if (tid < DD) { sB1[tid] = b1[tid]; sB2[tid] = b2[tid]; }
    if (tid < PP) sMind[tid] = 0x7F7FFFFF;   // FLT_MAX bits (all dists >= 0)
    __syncthreads();
    if (tid < PP) {   // ||p||^2 per prototype
        const float* pr = sP + tid * DD;
        float s = 0.f;
        #pragma unroll 8
        for (int d = 0; d < DD; d++) s += pr[d] * pr[d];
        sP2[tid] = s;
    }
    __syncthreads();

    const float* xg = x + (size_t)n * CIN * HW;

    // ---- 7 spatial sub-tiles of 128 positions ----
    for (int st = 0; st < 7; st++) {
        const int s0 = st * STILE;
        const int validCnt = HW - s0;   // >=128 except last tile (16)

        // ===== GEMM1: h[s][d] = relu(sum_c x[c][s] * W1[d][c] + b1[d]) =====
        u64 acc01[4], acc23[4];
        #pragma unroll
        for (int i = 0; i < 4; i++) { acc01[i] = 0ull; acc23[i] = 0ull; }

        for (int kc = 0; kc < CIN / KC; kc++) {
            __syncthreads();   // protect sXS vs prior chunk's readers
            // stage x chunk [KC][STILE], coalesced rows of 128
            #pragma unroll
            for (int j = 0; j < (KC * STILE) / THREADS; j++) {
                int i  = j * THREADS + tid;
                int k  = i >> 7;         // /128
                int sl = i & 127;
                int gs = s0 + sl;
                sXS[i] = (gs < HW) ? xg[(kc * KC + k) * HW + gs] : 0.f;
            }
            __syncthreads();
            const float* wrow = sW1 + dbase * CIN + kc * KC;
            #pragma unroll
            for (int k4 = 0; k4 < KC; k4 += 4) {
                float4 w4[4];
                #pragma unroll
                for (int di = 0; di < 4; di++)
                    w4[di] = *(const float4*)(wrow + di * CIN + k4);
                #pragma unroll
                for (int kk = 0; kk < 4; kk++) {
                    const float4 a = *(const float4*)(sXS + (k4 + kk) * STILE + sbase);
                    const u64 aA = pack2(a.x, a.y);
                    const u64 aB = pack2(a.z, a.w);
                    #pragma unroll
                    for (int di = 0; di < 4; di++) {
                        const u64 wd = dup2(((const float*)&w4[di])[kk]);
                        fma2(acc01[di], aA, wd);
                        fma2(acc23[di], aB, wd);
                    }
                }
            }
        }
        // relu(+b1), store h transposed [d][s]; zero per-position ||f||^2
        #pragma unroll
        for (int di = 0; di < 4; di++) {
            const float b = sB1[dbase + di];
            const float2 p01 = unpk(acc01[di]);
            const float2 p23 = unpk(acc23[di]);
            float4 v;
            v.x = fmaxf(p01.x + b, 0.f);
            v.y = fmaxf(p01.y + b, 0.f);
            v.z = fmaxf(p23.x + b, 0.f);
            v.w = fmaxf(p23.y + b, 0.f);
            *(float4*)(sHS + (dbase + di) * STILE + sbase) = v;
        }
        if (tid < STILE) sX2[tid] = 0.f;
        __syncthreads();

        // ===== GEMM2: f[s][d2] = sigmoid(sum_d1 h[d1][s] * W2[d2][d1] + b2) =====
        u64 bacc01[4], bacc23[4];
        #pragma unroll
        for (int i = 0; i < 4; i++) { bacc01[i] = 0ull; bacc23[i] = 0ull; }
        {
            const float* wrow = sW2 + dbase * DD;
            #pragma unroll
            for (int k4 = 0; k4 < DD; k4 += 4) {
                float4 w4[4];
                #pragma unroll
                for (int di = 0; di < 4; di++)
                    w4[di] = *(const float4*)(wrow + di * DD + k4);
                #pragma unroll
                for (int kk = 0; kk < 4; kk++) {
                    const float4 a = *(const float4*)(sHS + (k4 + kk) * STILE + sbase);
                    const u64 aA = pack2(a.x, a.y);
                    const u64 aB = pack2(a.z, a.w);
                    #pragma unroll
                    for (int di = 0; di < 4; di++) {
                        const u64 wd = dup2(((const float*)&w4[di])[kk]);
                        fma2(bacc01[di], aA, wd);
                        fma2(bacc23[di], aB, wd);
                    }
                }
            }
        }
        // sigmoid, accumulate ||f||^2 per position, store f transposed [d][s]
        float xpart[4] = {0.f, 0.f, 0.f, 0.f};
        #pragma unroll
        for (int di = 0; di < 4; di++) {
            const float b = sB2[dbase + di];
            const float2 p01 = unpk(bacc01[di]);
            const float2 p23 = unpk(bacc23[di]);
            float4 v;
            v.x = 1.f / (1.f + __expf(-(p01.x + b)));
            v.y = 1.f / (1.f + __expf(-(p01.y + b)));
            v.z = 1.f / (1.f + __expf(-(p23.x + b)));
            v.w = 1.f / (1.f + __expf(-(p23.y + b)));
            xpart[0] += v.x * v.x;
            xpart[1] += v.y * v.y;
            xpart[2] += v.z * v.z;
            xpart[3] += v.w * v.w;
            *(float4*)(sFS + (dbase + di) * STILE + sbase) = v;
        }
        #pragma unroll
        for (int si = 0; si < 4; si++) atomicAdd(&sX2[sbase + si], xpart[si]);
        __syncthreads();

        // ===== GEMM3: xp[s][p]; dist = relu(x2 - 2*xp + p2); running min =====
        // 4 prototypes per thread, 4 chunks of 64 (last chunk: groups >=2 idle).
        float xv[4];
        #pragma unroll
        for (int si = 0; si < 4; si++) xv[si] = sX2[sbase + si];

        for (int pc = 0; pc < 4; pc++) {
            const int pbase = pc * 64 + dbase;   // warp-uniform
            if (pbase >= PP) break;
            u64 pacc01[4], pacc23[4];
            #pragma unroll
            for (int i = 0; i < 4; i++) { pacc01[i] = 0ull; pacc23[i] = 0ull; }
            const float* prow = sP + pbase * DD;
            #pragma unroll
            for (int k4 = 0; k4 < DD; k4 += 4) {
                float4 w4[4];
                #pragma unroll
                for (int pj = 0; pj < 4; pj++)
                    w4[pj] = *(const float4*)(prow + pj * DD + k4);
                #pragma unroll
                for (int kk = 0; kk < 4; kk++) {
                    const float4 a = *(const float4*)(sFS + (k4 + kk) * STILE + sbase);
                    const u64 aA = pack2(a.x, a.y);
                    const u64 aB = pack2(a.z, a.w);
                    #pragma unroll
                    for (int pj = 0; pj < 4; pj++) {
                        const u64 wd = dup2(((const float*)&w4[pj])[kk]);
                        fma2(pacc01[pj], aA, wd);
                        fma2(pacc23[pj], aB, wd);
                    }
                }
            }
            #pragma unroll
            for (int pj = 0; pj < 4; pj++) {
                const float pn2 = sP2[pbase + pj];
                const float2 d01 = unpk(pacc01[pj]);
                const float2 d23 = unpk(pacc23[pj]);
                const float dv[4] = {d01.x, d01.y, d23.x, d23.y};
                float m = 3.402823466e+38f;
                #pragma unroll
                for (int si = 0; si < 4; si++) {
                    float d = xv[si] - 2.f * dv[si] + pn2;
                    d = fmaxf(d, 0.f);
                    if (sbase + si < validCnt) m = fminf(m, d);
                }
                #pragma unroll
                for (int o = 16; o > 0; o >>= 1)
                    m = fminf(m, __shfl_xor_sync(0xffffffffu, m, o));
                if (lane == 0)
                    atomicMin(&sMind[pbase + pj], __float_as_int(m));
            }
        }
        // no sync needed here: next iteration syncs before touching shared state
    }
    __syncthreads();

    // ---- Outputs ----
    if (tid < PP)
        out_mind[n * PP + tid] = __int_as_float(sMind[tid]);
    if (tid < NCLS * 32) {
        const int cls = tid >> 5;
        float ssum = 0.f;
        for (int p = lane; p < PP; p += 32)
            ssum += __int_as_float(sMind[p]) * lastW[cls * PP + p];
        #pragma unroll
        for (int o = 16; o > 0; o >>= 1)
            ssum += __shfl_xor_sync(0xffffffffu, ssum, o);
        if (lane == 0)
            out_logits[n * NCLS + cls] = lastB[cls] - ssum;   // act = -min_dist
    }
}

extern "C" void kernel_launch(void* const* d_in, const int* in_sizes, int n_in,
                              void* d_out, int out_size) {
    (void)in_sizes; (void)n_in; (void)out_size;
    const float* x      = (const float*)d_in[0];
    const float* W1     = (const float*)d_in[1];
    const float* b1     = (const float*)d_in[2];
    const float* W2     = (const float*)d_in[3];
    const float* b2     = (const float*)d_in[4];
    const float* proto  = (const float*)d_in[5];
    const float* lastW  = (const float*)d_in[6];
    const float* lastB  = (const float*)d_in[7];
    float* out        = (float*)d_out;
    float* out_logits = out;                 // (256,10)
    float* out_mind   = out + NB * NCLS;     // (256,200)

    cudaFuncSetAttribute(proto_fused_kernel,
                         cudaFuncAttributeMaxDynamicSharedMemorySize, SMEM_BYTES);
    proto_fused_kernel<<<NB, THREADS, SMEM_BYTES>>>(
        x, W1, b1, W2, b2, proto, lastW, lastB, out_logits, out_mind);
}

// round 6
// speedup vs baseline: 1.3241x; 1.0061x over previous
#include <cuda_runtime.h>
#include <math.h>

// Problem constants
#define NB    256   // batch
#define CIN   256   // input channels
#define HW    784   // 28*28 spatial
#define DD    64    // prototype channel dim
#define PP    200   // num prototypes
#define NCLS  10

constexpr int STILE   = 128;  // spatial positions per sub-tile
constexpr int KC      = 32;   // k-chunk for GEMM1 x-staging
constexpr int THREADS = 512;

// Shared memory layout (float offsets) — weights stored TRANSPOSED
constexpr int OFF_W1T = 0;                        // [256][64]  W1^T: [c][d]
constexpr int OFF_W2T = OFF_W1T + CIN * DD;       // [64][64]   W2^T: [d1][d2]
constexpr int OFF_PT  = OFF_W2T + DD * DD;        // [64][200]  P^T:  [c][p]
constexpr int OFF_P2  = OFF_PT  + DD * PP;        // [200]
constexpr int OFF_B1  = OFF_P2  + PP;             // [64]
constexpr int OFF_B2  = OFF_B1  + DD;             // [64]
constexpr int OFF_X2  = OFF_B2  + DD;             // [128]
constexpr int OFF_MIN = OFF_X2  + STILE;          // [200] (int bits)
constexpr int OFF_XS  = ((OFF_MIN + PP + 3) / 4) * 4;  // [KC][128]
constexpr int OFF_HS  = OFF_XS + KC * STILE;      // [64][128]
constexpr int OFF_FS  = OFF_HS + DD * STILE;      // [64][128]
constexpr int SMEM_FLOATS = OFF_FS + DD * STILE;
constexpr int SMEM_BYTES  = SMEM_FLOATS * 4;      // ~217.7 KB

typedef unsigned long long u64;

// ---- packed f32x2 helpers (FFMA2 — PTX-only on sm_103a) ----
__device__ __forceinline__ u64 dup2(float v) {
    u64 r; asm("mov.b64 %0, {%1,%1};" : "=l"(r) : "f"(v)); return r;
}
__device__ __forceinline__ void fma2(u64& d, u64 a, u64 b) {
    asm("fma.rn.f32x2 %0, %1, %2, %0;" : "+l"(d) : "l"(a), "l"(b));
}
__device__ __forceinline__ float2 unpk(u64 v) {
    float lo, hi; asm("mov.b64 {%0,%1}, %2;" : "=f"(lo), "=f"(hi) : "l"(v));
    return make_float2(lo, hi);
}

__global__ __launch_bounds__(THREADS, 1)
void proto_fused_kernel(const float* __restrict__ x,
                        const float* __restrict__ W1,
                        const float* __restrict__ b1,
                        const float* __restrict__ W2,
                        const float* __restrict__ b2,
                        const float* __restrict__ proto,
                        const float* __restrict__ lastW,
                        const float* __restrict__ lastB,
                        float* __restrict__ out_logits,
                        float* __restrict__ out_mind)
{
    extern __shared__ float sm[];
    float* sW1T = sm + OFF_W1T;
    float* sW2T = sm + OFF_W2T;
    float* sPT  = sm + OFF_PT;
    float* sP2  = sm + OFF_P2;
    float* sB1  = sm + OFF_B1;
    float* sB2  = sm + OFF_B2;
    float* sX2  = sm + OFF_X2;
    float* sXS  = sm + OFF_XS;
    float* sHS  = sm + OFF_HS;
    float* sFS  = sm + OFF_FS;
    int*   sMind = (int*)(sm + OFF_MIN);

    const int tid   = threadIdx.x;
    const int n     = blockIdx.x;
    const int lane  = tid & 31;
    const int grp   = tid >> 5;          // 0..15
    const int ogrp  = grp & 7;           // 8 output groups (d / proto)
    const int shalf = grp >> 3;          // 2 spatial halves
    const int obase = ogrp * 8;          // 8 outputs per thread
    const int sbase = shalf * 64 + lane * 2;   // 2 spatial positions per thread

    // ---- Prologue: stage + transpose weights into smem ----
    {   // stage W1 (linear, coalesced) into HS+FS temp; W2 into XS temp
        float* tmpBig = sHS;       // 16384 floats available (HS+FS contiguous)
        float* tmpW2  = sXS;       // 4096 floats
        const float4* g1 = (const float4*)W1;
        const float4* g2 = (const float4*)W2;
        for (int i = tid; i < (DD * CIN) / 4; i += THREADS) ((float4*)tmpBig)[i] = g1[i];
        for (int i = tid; i < (DD * DD) / 4; i += THREADS)  ((float4*)tmpW2)[i]  = g2[i];
        if (tid < DD) { sB1[tid] = b1[tid]; sB2[tid] = b2[tid]; }
        if (tid < PP) sMind[tid] = 0x7F7FFFFF;   // FLT_MAX bits
        __syncthreads();
        for (int i = tid; i < DD * CIN; i += THREADS) {
            int d = i >> 8, c = i & 255;           // W1[d][c]
            sW1T[c * DD + d] = tmpBig[i];
        }
        for (int i = tid; i < DD * DD; i += THREADS) {
            int d2 = i >> 6, d1 = i & 63;          // W2[d2][d1]
            sW2T[d1 * DD + d2] = tmpW2[i];
        }
        __syncthreads();
        const float4* gp = (const float4*)proto;
        for (int i = tid; i < (PP * DD) / 4; i += THREADS) ((float4*)tmpBig)[i] = gp[i];
        __syncthreads();
        for (int i = tid; i < PP * DD; i += THREADS) {
            int p = i >> 6, c = i & 63;            // proto[p][c]
            sPT[c * PP + p] = tmpBig[i];
        }
        __syncthreads();
        if (tid < PP) {                            // ||p||^2 from P^T column
            float s = 0.f;
            #pragma unroll 8
            for (int c = 0; c < DD; c++) { float v = sPT[c * PP + tid]; s += v * v; }
            sP2[tid] = s;
        }
        __syncthreads();
    }

    const float* xg = x + (size_t)n * CIN * HW;

    // ---- 7 spatial sub-tiles of 128 positions ----
    for (int st = 0; st < 7; st++) {
        const int s0 = st * STILE;
        const int validCnt = HW - s0;   // >=128 except last tile (16)

        // ===== GEMM1: h[s][d] = relu(sum_c x[c][s]*W1[d][c] + b1[d]) =====
        u64 a0[4], a1[4];
        #pragma unroll
        for (int j = 0; j < 4; j++) { a0[j] = 0ull; a1[j] = 0ull; }

        for (int kc = 0; kc < CIN / KC; kc++) {
            __syncthreads();   // protect sXS vs prior readers
            #pragma unroll
            for (int j = 0; j < (KC * STILE) / THREADS; j++) {
                int i  = j * THREADS + tid;
                int k  = i >> 7;
                int sl = i & 127;
                int gs = s0 + sl;
                sXS[i] = (gs < HW) ? xg[(kc * KC + k) * HW + gs] : 0.f;
            }
            __syncthreads();
            const float* wb = sW1T + (kc * KC) * DD + obase;
            #pragma unroll
            for (int k = 0; k < KC; k++) {
                const float2 av = *(const float2*)(sXS + k * STILE + sbase);
                const u64 d0 = dup2(av.x);
                const u64 d1 = dup2(av.y);
                const ulonglong2 wA = *(const ulonglong2*)(wb + k * DD);
                const ulonglong2 wB = *(const ulonglong2*)(wb + k * DD + 4);
                fma2(a0[0], d0, wA.x); fma2(a1[0], d1, wA.x);
                fma2(a0[1], d0, wA.y); fma2(a1[1], d1, wA.y);
                fma2(a0[2], d0, wB.x); fma2(a1[2], d1, wB.x);
                fma2(a0[3], d0, wB.y); fma2(a1[3], d1, wB.y);
            }
        }
        // epilogue: +bias, relu, store h transposed [d][s]
        #pragma unroll
        for (int j = 0; j < 4; j++) {
            const int d = obase + 2 * j;
            const float bL = sB1[d], bH = sB1[d + 1];
            const float2 p0 = unpk(a0[j]);   // spatial s0: {d, d+1}
            const float2 p1 = unpk(a1[j]);   // spatial s1
            sHS[d * STILE + sbase]           = fmaxf(p0.x + bL, 0.f);
            sHS[d * STILE + sbase + 1]       = fmaxf(p1.x + bL, 0.f);
            sHS[(d + 1) * STILE + sbase]     = fmaxf(p0.y + bH, 0.f);
            sHS[(d + 1) * STILE + sbase + 1] = fmaxf(p1.y + bH, 0.f);
        }
        if (tid < STILE) sX2[tid] = 0.f;
        __syncthreads();

        // ===== GEMM2: f = sigmoid(W2 h + b2); accumulate ||f||^2 =====
        #pragma unroll
        for (int j = 0; j < 4; j++) { a0[j] = 0ull; a1[j] = 0ull; }
        {
            const float* wb = sW2T + obase;
            #pragma unroll
            for (int k = 0; k < DD; k++) {
                const float2 av = *(const float2*)(sHS + k * STILE + sbase);
                const u64 d0 = dup2(av.x);
                const u64 d1 = dup2(av.y);
                const ulonglong2 wA = *(const ulonglong2*)(wb + k * DD);
                const ulonglong2 wB = *(const ulonglong2*)(wb + k * DD + 4);
                fma2(a0[0], d0, wA.x); fma2(a1[0], d1, wA.x);
                fma2(a0[1], d0, wA.y); fma2(a1[1], d1, wA.y);
                fma2(a0[2], d0, wB.x); fma2(a1[2], d1, wB.x);
                fma2(a0[3], d0, wB.y); fma2(a1[3], d1, wB.y);
            }
        }
        float xs0 = 0.f, xs1 = 0.f;
        #pragma unroll
        for (int j = 0; j < 4; j++) {
            const int d = obase + 2 * j;
            const float bL = sB2[d], bH = sB2[d + 1];
            const float2 p0 = unpk(a0[j]);
            const float2 p1 = unpk(a1[j]);
            const float f00 = 1.f / (1.f + __expf(-(p0.x + bL)));
            const float f10 = 1.f / (1.f + __expf(-(p1.x + bL)));
            const float f01 = 1.f / (1.f + __expf(-(p0.y + bH)));
            const float f11 = 1.f / (1.f + __expf(-(p1.y + bH)));
            xs0 += f00 * f00 + f01 * f01;
            xs1 += f10 * f10 + f11 * f11;
            sFS[d * STILE + sbase]           = f00;
            sFS[d * STILE + sbase + 1]       = f10;
            sFS[(d + 1) * STILE + sbase]     = f01;
            sFS[(d + 1) * STILE + sbase + 1] = f11;
        }
        atomicAdd(&sX2[sbase], xs0);
        atomicAdd(&sX2[sbase + 1], xs1);
        __syncthreads();

        // ===== GEMM3: xp; dist = relu(x2 - 2 xp + p2); running min =====
        const float xv0 = sX2[sbase];
        const float xv1 = sX2[sbase + 1];
        const bool v0 = (sbase < validCnt);
        const bool v1 = (sbase + 1 < validCnt);

        for (int pc = 0; pc < 4; pc++) {
            const int pbase = pc * 64 + obase;   // warp-uniform
            if (pbase >= PP) break;
            u64 c0[4], c1[4];
            #pragma unroll
            for (int j = 0; j < 4; j++) { c0[j] = 0ull; c1[j] = 0ull; }
            const float* wp = sPT + pbase;
            #pragma unroll
            for (int k = 0; k < DD; k++) {
                const float2 av = *(const float2*)(sFS + k * STILE + sbase);
                const u64 d0 = dup2(av.x);
                const u64 d1 = dup2(av.y);
                const ulonglong2 wA = *(const ulonglong2*)(wp + k * PP);
                const ulonglong2 wB = *(const ulonglong2*)(wp + k * PP + 4);
                fma2(c0[0], d0, wA.x); fma2(c1[0], d1, wA.x);
                fma2(c0[1], d0, wA.y); fma2(c1[1], d1, wA.y);
                fma2(c0[2], d0, wB.x); fma2(c1[2], d1, wB.x);
                fma2(c0[3], d0, wB.y); fma2(c1[3], d1, wB.y);
            }
            #pragma unroll
            for (int j = 0; j < 4; j++) {
                const int p = pbase + 2 * j;
                const float n0 = sP2[p], n1 = sP2[p + 1];
                const float2 q0 = unpk(c0[j]);   // s0: {p, p+1}
                const float2 q1 = unpk(c1[j]);   // s1
                const float e00 = fmaxf(xv0 - 2.f * q0.x + n0, 0.f);
                const float e10 = fmaxf(xv1 - 2.f * q1.x + n0, 0.f);
                const float e01 = fmaxf(xv0 - 2.f * q0.y + n1, 0.f);
                const float e11 = fmaxf(xv1 - 2.f * q1.y + n1, 0.f);
                float m0 = 3.402823466e+38f, m1 = 3.402823466e+38f;
                if (v0) { m0 = e00; m1 = e01; }
                if (v1) { m0 = fminf(m0, e10); m1 = fminf(m1, e11); }
                #pragma unroll
                for (int o = 16; o > 0; o >>= 1) {
                    m0 = fminf(m0, __shfl_xor_sync(0xffffffffu, m0, o));
                    m1 = fminf(m1, __shfl_xor_sync(0xffffffffu, m1, o));
                }
                if (lane == 0) {
                    atomicMin(&sMind[p],     __float_as_int(m0));
                    atomicMin(&sMind[p + 1], __float_as_int(m1));
                }
            }
        }
        // next iteration's first __syncthreads protects shared state
    }
    __syncthreads();

    // ---- Outputs ----
    if (tid < PP)
        out_mind[n * PP + tid] = __int_as_float(sMind[tid]);
    if (tid < NCLS * 32) {
        const int cls = tid >> 5;
        float ssum = 0.f;
        for (int p = lane; p < PP; p += 32)
            ssum += __int_as_float(sMind[p]) * lastW[cls * PP + p];
        #pragma unroll
        for (int o = 16; o > 0; o >>= 1)
            ssum += __shfl_xor_sync(0xffffffffu, ssum, o);
        if (lane == 0)
            out_logits[n * NCLS + cls] = lastB[cls] - ssum;   // act = -min_dist
    }
}

extern "C" void kernel_launch(void* const* d_in, const int* in_sizes, int n_in,
                              void* d_out, int out_size) {
    (void)in_sizes; (void)n_in; (void)out_size;
    const float* x      = (const float*)d_in[0];
    const float* W1     = (const float*)d_in[1];
    const float* b1     = (const float*)d_in[2];
    const float* W2     = (const float*)d_in[3];
    const float* b2     = (const float*)d_in[4];
    const float* proto  = (const float*)d_in[5];
    const float* lastW  = (const float*)d_in[6];
    const float* lastB  = (const float*)d_in[7];
    float* out        = (float*)d_out;
    float* out_logits = out;                 // (256,10)
    float* out_mind   = out + NB * NCLS;     // (256,200)

    cudaFuncSetAttribute(proto_fused_kernel,
                         cudaFuncAttributeMaxDynamicSharedMemorySize, SMEM_BYTES);
    proto_fused_kernel<<<NB, THREADS, SMEM_BYTES>>>(
        x, W1, b1, W2, b2, proto, lastW, lastB, out_logits, out_mind);
}